// round 17
// baseline (speedup 1.0000x reference)
#include <cuda_runtime.h>
#include <cuda_bf16.h>
#include <cstdint>

#define BD 4
#define CD 256
#define HD 56
#define WD 56
#define GD 16
#define GCD 16
#define POSN (BD*HD*WD)   // 12544
#define IN1 2112
#define OUT1 96
#define OWD 112
#define KHALF 1056        // IN1/2 (k units)
#define N2 192

// Scratch (device globals)
__device__ float    g_desc[(size_t)IN1 * POSN];      // [feature][pos] ~106 MB
__device__ float    g_rp[2ull * POSN * OUT1];        // split-K partials (pre-BN)
__device__ uint32_t g_w1ph[(size_t)(IN1/2) * OUT1];  // bf16x2-packed hi, [kp][n]
__device__ uint32_t g_w1pl[(size_t)(IN1/2) * OUT1];  // bf16x2-packed lo residual
__device__ uint32_t g_w23ph[(size_t)(OUT1/2) * N2];  // bf16x2 [kp][n] for gemm2
__device__ uint32_t g_w23pl[(size_t)(OUT1/2) * N2];
__device__ float    g_wab[(size_t)POSN * N2];        // wa | wb

// ---------------------------------------------------------------------------
// helpers
// ---------------------------------------------------------------------------
__device__ __forceinline__ void mma_bf16(float* c, const uint32_t* a, const uint32_t* b) {
    asm volatile(
        "mma.sync.aligned.m16n8k16.row.col.f32.bf16.bf16.f32 "
        "{%0,%1,%2,%3}, {%4,%5,%6,%7}, {%8,%9}, {%0,%1,%2,%3};"
        : "+f"(c[0]), "+f"(c[1]), "+f"(c[2]), "+f"(c[3])
        : "r"(a[0]), "r"(a[1]), "r"(a[2]), "r"(a[3]), "r"(b[0]), "r"(b[1]));
}
// pack k-pair: lo half = even k, hi half = odd k
__device__ __forceinline__ uint32_t packbf(float klo, float khi) {
    uint32_t r;
    asm("cvt.rn.bf16x2.f32 %0, %1, %2;" : "=r"(r) : "f"(khi), "f"(klo));
    return r;
}
__device__ __forceinline__ float bfround(float v) {
    return __bfloat162float(__float2bfloat16(v));
}

// ---------------------------------------------------------------------------
// K0a: pack w1 -> bf16x2 hi/lo, [kp][n]  (kp = k/2)
// ---------------------------------------------------------------------------
__global__ __launch_bounds__(256) void w1pack_kernel(const float* __restrict__ w1) {
    int idx = blockIdx.x * 256 + threadIdx.x;
    if (idx >= (IN1/2) * OUT1) return;
    int n  = idx % OUT1;
    int kp = idx / OUT1;
    float v0 = w1[(unsigned)n * IN1 + 2*kp];
    float v1 = w1[(unsigned)n * IN1 + 2*kp + 1];
    float h0 = bfround(v0), h1 = bfround(v1);
    g_w1ph[idx] = packbf(h0, h1);
    g_w1pl[idx] = packbf(v0 - h0, v1 - h1);
}

// ---------------------------------------------------------------------------
// K0b: pack [w2|w3] -> bf16x2 hi/lo, [kp][n], kp<48, n<192
// ---------------------------------------------------------------------------
__global__ __launch_bounds__(256) void w23pack_kernel(
    const float* __restrict__ w2, const float* __restrict__ w3) {
    int idx = blockIdx.x * 256 + threadIdx.x;
    if (idx >= (OUT1/2) * N2) return;
    int n  = idx % N2;
    int kp = idx / N2;
    int k0 = 2*kp, k1 = 2*kp + 1;
    float v0 = (n < OUT1) ? w2[(unsigned)n * OUT1 + k0] : w3[(unsigned)(n - OUT1) * OUT1 + k0];
    float v1 = (n < OUT1) ? w2[(unsigned)n * OUT1 + k1] : w3[(unsigned)(n - OUT1) * OUT1 + k1];
    float h0 = bfround(v0), h1 = bfround(v1);
    g_w23ph[idx] = packbf(h0, h1);
    g_w23pl[idx] = packbf(v0 - h0, v1 - h1);
}

// ---------------------------------------------------------------------------
// Scrambled-unfold taps, 64-padded rows (R16, proven)
// ---------------------------------------------------------------------------
__device__ __forceinline__ void load_taps(const float* __restrict__ x,
                                          int b, int g, int h2,
                                          float (*xs)[3][3][64], int tid) {
    const unsigned cbase = (unsigned)(b*CD + g*GCD);
    const int wp = tid & 63;
    const int ww = wp - 1;
    const bool wok = (ww >= 0 && ww < WD);
    for (int t = tid >> 6; t < GCD * 9; t += 2) {
        int kh = t % 3;
        int kw = (t / 3) % 3;
        int gc = t / 9;
        int m  = kw * 56 + h2;
        int hh = m / 3 + kh - 1;
        float v = 0.f;
        if (wok && hh >= 0 && hh < HD)
            v = x[((cbase + gc)*HD + hh)*WD + ww];
        xs[gc][kw][kh][wp] = v;
    }
}

// ---------------------------------------------------------------------------
// K1: descriptor build (R16, proven)
// ---------------------------------------------------------------------------
__global__ __launch_bounds__(128) void desc_kernel(const float* __restrict__ x) {
    const int g = blockIdx.x, h2 = blockIdx.y, b = blockIdx.z;
    __shared__ float xs[GCD][3][3][64];   // 36864 B

    const int tid = threadIdx.x;
    load_taps(x, b, g, h2, xs, tid);
    __syncthreads();

    const int jv0 = h2 % 3, jv1 = (56 + h2) % 3, jv2 = (112 + h2) % 3;
    const unsigned posBase = (unsigned)(b*HD + h2)*WD;

    for (int it = tid; it < GCD * WD; it += 128) {
        int w  = it % WD;
        int gc = it / WD;
        float T[3][3];
        #pragma unroll
        for (int kh = 0; kh < 3; kh++) {
            T[kh][0] = xs[gc][0][kh][w + jv0];
            T[kh][1] = xs[gc][1][kh][w + jv1];
            T[kh][2] = xs[gc][2][kh][w + jv2];
        }
        unsigned f2 = (unsigned)(576 + g*48 + gc*3);
        unsigned f3 = (unsigned)(1344 + g*48 + gc*3);
        #pragma unroll
        for (int kw = 0; kw < 3; kw++) {
            float m = fmaxf(T[0][kw], fmaxf(T[1][kw], T[2][kw]));
            g_desc[(f2 + kw)*POSN + posBase + w] = m;
        }
        #pragma unroll
        for (int kh = 0; kh < 3; kh++) {
            float m = fmaxf(T[kh][0], fmaxf(T[kh][1], T[kh][2]));
            g_desc[(f3 + kh)*POSN + posBase + w] = m;
        }
    }

    const int jvv[3] = {jv0, jv1, jv2};
    for (int it = tid; it < 4 * WD; it += 128) {
        int w  = it % WD;
        int jc = it / WD;
        unsigned f1 = (unsigned)(g*36 + jc*9);
        #pragma unroll
        for (int kh = 0; kh < 3; kh++) {
            #pragma unroll
            for (int kw = 0; kw < 3; kw++) {
                int wp = w + jvv[kw];
                float m = xs[jc][kw][kh][wp];
                m = fmaxf(m, xs[jc + 4 ][kw][kh][wp]);
                m = fmaxf(m, xs[jc + 8 ][kw][kh][wp]);
                m = fmaxf(m, xs[jc + 12][kw][kh][wp]);
                g_desc[(f1 + kh*3 + kw)*POSN + posBase + w] = m;
            }
        }
    }
}

// ---------------------------------------------------------------------------
// K2: GEMM1 3xBF16 m16n8k16, K-tile 48 k (24 kp) -> 22 iters.
// BM=64, BN=96. 256 thr = 8 warps (2m x 4n). smem ~33 KB.
// ---------------------------------------------------------------------------
#define GBM 64
#define APR 72
#define BPR 104

__global__ __launch_bounds__(256) void gemm_tc_kernel() {
    __shared__ uint32_t Aph[24][APR], Apl[24][APR];
    __shared__ uint32_t Bph[24][BPR], Bpl[24][BPR];

    const int tid  = threadIdx.x;
    const int warp = tid >> 5;
    const int lane = tid & 31;
    const int wm = warp >> 2;          // 0..1 (m)
    const int wn = warp & 3;           // 0..3 (n)
    const int ar = lane >> 2;          // 0..7
    const int ac = lane & 3;           // 0..3
    const unsigned row0 = blockIdx.x * GBM;
    const int khalf = blockIdx.y;
    const unsigned kbase = khalf * KHALF;
    const unsigned kpbase = kbase >> 1;

    float c[2][3][4];
    #pragma unroll
    for (int mt = 0; mt < 2; mt++)
        #pragma unroll
        for (int nt = 0; nt < 3; nt++)
            #pragma unroll
            for (int q = 0; q < 4; q++) c[mt][nt][q] = 0.f;

    const int akp = tid >> 5;          // 0..7; handles kp rows akp, +8, +16
    const int am2 = lane * 2;          // 0..62 (m pair)

    for (int k0 = 0; k0 < KHALF; k0 += 48) {
        // A tile: 48 k x 64 m. 3 kp rows per thread.
        #pragma unroll
        for (int r = 0; r < 3; r++) {
            int kpr = akp + r*8;       // 0..23
            unsigned krow = kbase + k0 + 2*kpr;
            float2 v0 = *reinterpret_cast<const float2*>(&g_desc[(size_t)krow*POSN + row0 + am2]);
            float2 v1 = *reinterpret_cast<const float2*>(&g_desc[(size_t)(krow+1)*POSN + row0 + am2]);
            float h00 = bfround(v0.x), h10 = bfround(v1.x);
            float h01 = bfround(v0.y), h11 = bfround(v1.y);
            *reinterpret_cast<uint2*>(&Aph[kpr][am2]) =
                make_uint2(packbf(h00, h10), packbf(h01, h11));
            *reinterpret_cast<uint2*>(&Apl[kpr][am2]) =
                make_uint2(packbf(v0.x - h00, v1.x - h10),
                           packbf(v0.y - h01, v1.y - h11));
        }
        // B tile: 24 kp x 96 n (2304 u32 per array, 9 per thread)
        {
            const unsigned base = (kpbase + (unsigned)(k0 >> 1)) * OUT1;
            #pragma unroll
            for (int i = 0; i < 9; i++) {
                int idx = tid + (i << 8);
                int n = idx % OUT1, kp = idx / OUT1;
                Bph[kp][n] = g_w1ph[base + idx];
                Bpl[kp][n] = g_w1pl[base + idx];
            }
        }
        __syncthreads();

        #pragma unroll
        for (int ks = 0; ks < 3; ks++) {
            const int kb = ks * 8;
            uint32_t ah[2][4], al[2][4];
            #pragma unroll
            for (int mt = 0; mt < 2; mt++) {
                int mrow = wm*32 + mt*16 + ar;
                ah[mt][0] = Aph[kb+ac  ][mrow];   ah[mt][1] = Aph[kb+ac  ][mrow+8];
                ah[mt][2] = Aph[kb+ac+4][mrow];   ah[mt][3] = Aph[kb+ac+4][mrow+8];
                al[mt][0] = Apl[kb+ac  ][mrow];   al[mt][1] = Apl[kb+ac  ][mrow+8];
                al[mt][2] = Apl[kb+ac+4][mrow];   al[mt][3] = Apl[kb+ac+4][mrow+8];
            }
            uint32_t bh[3][2], bl[3][2];
            #pragma unroll
            for (int nt = 0; nt < 3; nt++) {
                int n = wn*24 + nt*8 + ar;
                bh[nt][0] = Bph[kb+ac][n];  bh[nt][1] = Bph[kb+ac+4][n];
                bl[nt][0] = Bpl[kb+ac][n];  bl[nt][1] = Bpl[kb+ac+4][n];
            }
            #pragma unroll
            for (int mt = 0; mt < 2; mt++)
                #pragma unroll
                for (int nt = 0; nt < 3; nt++) {
                    mma_bf16(c[mt][nt], ah[mt], bl[nt]);   // hi x lo
                    mma_bf16(c[mt][nt], al[mt], bh[nt]);   // lo x hi
                    mma_bf16(c[mt][nt], ah[mt], bh[nt]);   // hi x hi
                }
        }
        __syncthreads();
    }

    float* rp = &g_rp[(size_t)khalf * POSN * OUT1];
    #pragma unroll
    for (int nt = 0; nt < 3; nt++) {
        int n0 = wn*24 + nt*8 + 2*ac;
        #pragma unroll
        for (int mt = 0; mt < 2; mt++) {
            unsigned m0 = row0 + wm*32 + mt*16 + ar;
            *reinterpret_cast<float2*>(&rp[m0*OUT1 + n0]) =
                make_float2(c[mt][nt][0], c[mt][nt][1]);
            *reinterpret_cast<float2*>(&rp[(m0+8)*OUT1 + n0]) =
                make_float2(c[mt][nt][2], c[mt][nt][3]);
        }
    }
}

// ---------------------------------------------------------------------------
// K2b: GEMM2, now 3xBF16 + N-split. grid (196, 2): BM=64 m x BN=96 n.
// wab[:, nhalf*96 : +96] = relu(BN(rp0+rp1)) @ w23[:, nhalf] + bias.
// K=96: 6 chunks of 16 k (8 kp). A packed on the fly from r.
// ---------------------------------------------------------------------------
__global__ __launch_bounds__(256) void gemm2_kernel(
    const float* __restrict__ gamma, const float* __restrict__ beta,
    const float* __restrict__ mean,  const float* __restrict__ var,
    const float* __restrict__ b2,    const float* __restrict__ b3)
{
    __shared__ uint32_t A2ph[8][APR], A2pl[8][APR];
    __shared__ uint32_t B2ph[8][BPR], B2pl[8][BPR];
    __shared__ float sS[OUT1], sB[OUT1];

    const int tid  = threadIdx.x;
    const int warp = tid >> 5;
    const int lane = tid & 31;
    const int wm = warp >> 2;          // 0..1 (m)
    const int wn = warp & 3;           // 0..3 (n)
    const int ar = lane >> 2;          // 0..7
    const int ac = lane & 3;           // 0..3
    const unsigned row0 = blockIdx.x * GBM;
    const int noff = blockIdx.y * 96;  // n half offset

    if (tid < OUT1) {
        float s = gamma[tid] * rsqrtf(var[tid] + 1e-5f);
        sS[tid] = s;
        sB[tid] = beta[tid] - mean[tid] * s;
    }
    __syncthreads();

    float c[2][3][4];
    #pragma unroll
    for (int mt = 0; mt < 2; mt++)
        #pragma unroll
        for (int nt = 0; nt < 3; nt++)
            #pragma unroll
            for (int q = 0; q < 4; q++) c[mt][nt][q] = 0.f;

    const int am  = tid >> 2;          // 0..63 (m row)
    const int akq = tid & 3;           // 0..3 (k quad)

    #pragma unroll
    for (int k0 = 0; k0 < OUT1; k0 += 16) {
        // A: compute r for 4 k at (row0+am, k0+akq*4), pack 2 bf16x2 pairs
        {
            int kk = k0 + akq*4;
            unsigned base = (row0 + am)*OUT1 + kk;
            float4 p0 = *reinterpret_cast<const float4*>(&g_rp[base]);
            float4 p1 = *reinterpret_cast<const float4*>(&g_rp[(size_t)POSN*OUT1 + base]);
            float r0 = fmaxf(fmaf(p0.x + p1.x, sS[kk  ], sB[kk  ]), 0.f);
            float r1 = fmaxf(fmaf(p0.y + p1.y, sS[kk+1], sB[kk+1]), 0.f);
            float r2 = fmaxf(fmaf(p0.z + p1.z, sS[kk+2], sB[kk+2]), 0.f);
            float r3 = fmaxf(fmaf(p0.w + p1.w, sS[kk+3], sB[kk+3]), 0.f);
            float h0 = bfround(r0), h1 = bfround(r1);
            float h2 = bfround(r2), h3 = bfround(r3);
            A2ph[akq*2    ][am] = packbf(h0, h1);
            A2pl[akq*2    ][am] = packbf(r0 - h0, r1 - h1);
            A2ph[akq*2 + 1][am] = packbf(h2, h3);
            A2pl[akq*2 + 1][am] = packbf(r2 - h2, r3 - h3);
        }
        // B: 8 kp x 96 n from packed w23 (768 u32 per array, 3 per thread)
        {
            const unsigned kp0 = (unsigned)(k0 >> 1);
            #pragma unroll
            for (int i = 0; i < 3; i++) {
                int idx = tid + (i << 8);
                int n = idx % 96, kp = idx / 96;
                B2ph[kp][n] = g_w23ph[(kp0 + kp)*N2 + noff + n];
                B2pl[kp][n] = g_w23pl[(kp0 + kp)*N2 + noff + n];
            }
        }
        __syncthreads();

        uint32_t ah[2][4], al[2][4];
        #pragma unroll
        for (int mt = 0; mt < 2; mt++) {
            int mrow = wm*32 + mt*16 + ar;
            ah[mt][0] = A2ph[ac  ][mrow];   ah[mt][1] = A2ph[ac  ][mrow+8];
            ah[mt][2] = A2ph[ac+4][mrow];   ah[mt][3] = A2ph[ac+4][mrow+8];
            al[mt][0] = A2pl[ac  ][mrow];   al[mt][1] = A2pl[ac  ][mrow+8];
            al[mt][2] = A2pl[ac+4][mrow];   al[mt][3] = A2pl[ac+4][mrow+8];
        }
        uint32_t bh[3][2], bl[3][2];
        #pragma unroll
        for (int nt = 0; nt < 3; nt++) {
            int n = wn*24 + nt*8 + ar;
            bh[nt][0] = B2ph[ac][n];  bh[nt][1] = B2ph[ac+4][n];
            bl[nt][0] = B2pl[ac][n];  bl[nt][1] = B2pl[ac+4][n];
        }
        #pragma unroll
        for (int mt = 0; mt < 2; mt++)
            #pragma unroll
            for (int nt = 0; nt < 3; nt++) {
                mma_bf16(c[mt][nt], ah[mt], bl[nt]);
                mma_bf16(c[mt][nt], al[mt], bh[nt]);
                mma_bf16(c[mt][nt], ah[mt], bh[nt]);
            }
        __syncthreads();
    }

    // Epilogue: + bias, store g_wab slice
    #pragma unroll
    for (int nt = 0; nt < 3; nt++) {
        int nl = wn*24 + nt*8 + 2*ac;        // 0..95 local
        int ng = noff + nl;                  // global n in [0,192)
        float bias0 = (ng < OUT1) ? b2[ng] : b3[ng - OUT1];
        float bias1 = (ng + 1 < OUT1) ? b2[ng + 1] : b3[ng + 1 - OUT1];
        #pragma unroll
        for (int mt = 0; mt < 2; mt++) {
            unsigned m0 = row0 + wm*32 + mt*16 + ar;
            *reinterpret_cast<float2*>(&g_wab[(size_t)m0*N2 + ng]) =
                make_float2(c[mt][nt][0] + bias0, c[mt][nt][1] + bias1);
            *reinterpret_cast<float2*>(&g_wab[(size_t)(m0+8)*N2 + ng]) =
                make_float2(c[mt][nt][2] + bias0, c[mt][nt][3] + bias1);
        }
    }
}

// ---------------------------------------------------------------------------
// K3: apply (R16, proven)
// ---------------------------------------------------------------------------
__global__ __launch_bounds__(128) void apply_kernel(
    const float* __restrict__ x, float* __restrict__ out)
{
    const int g = blockIdx.x, h2 = blockIdx.y, b = blockIdx.z;
    __shared__ float xs[GCD][3][3][64];
    __shared__ float wab[WD][12];
    __shared__ float sms[WD*37];

    const int tid = threadIdx.x;
    const unsigned posBase = (unsigned)(b*HD + h2)*WD;

    for (int it = tid; it < WD * 12; it += 128) {
        int q = it % 12;
        int w = it / 12;
        int col = (q < 6) ? (g*6 + q) : (OUT1 + g*6 + q - 6);
        wab[w][q] = g_wab[(size_t)(posBase + w)*N2 + col];
    }
    load_taps(x, b, g, h2, xs, tid);
    __syncthreads();

    for (int it = tid; it < WD * 4; it += 128) {
        int t = it % 4;
        int w = it / 4;
        int nh = t >> 1, nw = t & 1;
        float e[9], m = -1e30f;
        #pragma unroll
        for (int kk = 0; kk < 9; kk++) {
            int kh = kk / 3, kw = kk % 3;
            e[kk] = wab[w][kh*2 + nh] * wab[w][6 + kw*2 + nw];
            m = fmaxf(m, e[kk]);
        }
        float s = 0.f;
        #pragma unroll
        for (int kk = 0; kk < 9; kk++) { e[kk] = expf(e[kk] - m); s += e[kk]; }
        float inv = 1.f / (s * 9.f);
        #pragma unroll
        for (int kk = 0; kk < 9; kk++) sms[w*37 + t*9 + kk] = e[kk] * inv;
    }
    __syncthreads();

    const int jv0 = h2 % 3, jv1 = (56 + h2) % 3, jv2 = (112 + h2) % 3;
    const int jvv[3] = {jv0, jv1, jv2};

    for (int it = tid; it < GCD * WD; it += 128) {
        int w  = it % WD;
        int gc = it / WD;
        float o[4] = {0.f, 0.f, 0.f, 0.f};
        #pragma unroll
        for (int kk = 0; kk < 9; kk++) {
            int kh = kk / 3, kw = kk % 3;
            float u = xs[gc][kw][kh][w + jvv[kw]];
            #pragma unroll
            for (int t = 0; t < 4; t++)
                o[t] = fmaf(u, sms[w*37 + t*9 + kk], o[t]);
        }
        int c = g*GCD + gc;
        unsigned ob = ((unsigned)(b*CD + c))*OWD + 2*h2;
        *reinterpret_cast<float2*>(&out[(size_t)ob*OWD + 2*w]) =
            make_float2(o[0], o[1]);
        *reinterpret_cast<float2*>(&out[(size_t)(ob+1)*OWD + 2*w]) =
            make_float2(o[2], o[3]);
    }
}

// ---------------------------------------------------------------------------
extern "C" void kernel_launch(void* const* d_in, const int* in_sizes, int n_in,
                              void* d_out, int out_size) {
    const float* x     = (const float*)d_in[0];
    const float* w1    = (const float*)d_in[1];
    const float* gamma = (const float*)d_in[2];
    const float* beta  = (const float*)d_in[3];
    const float* mean  = (const float*)d_in[4];
    const float* var   = (const float*)d_in[5];
    const float* w2    = (const float*)d_in[6];
    const float* b2    = (const float*)d_in[7];
    const float* w3    = (const float*)d_in[8];
    const float* b3    = (const float*)d_in[9];
    float* out = (float*)d_out;

    dim3 gridA(GD, HD, BD);   // (16, 56, 4)
    w1pack_kernel<<<((IN1/2)*OUT1 + 255)/256, 256>>>(w1);
    w23pack_kernel<<<((OUT1/2)*N2 + 255)/256, 256>>>(w2, w3);
    desc_kernel<<<gridA, 128>>>(x);
    gemm_tc_kernel<<<dim3(POSN / GBM, 2), 256>>>();
    gemm2_kernel<<<dim3(POSN / GBM, 2), 256>>>(gamma, beta, mean, var, b2, b3);
    apply_kernel<<<gridA, 128>>>(x, out);
}